// round 10
// baseline (speedup 1.0000x reference)
#include <cuda_runtime.h>
#include <math.h>

#define NN     50000
#define RR     4
#define DD     5
#define BB     8
#define TT     10
#define E_RECN 1500000
#define E_INN  200000
#define N_INN  17400
#define RNN    (RR * NN)   // 200000
#define IN_QUADS (E_INN / 4)   // 50000

#define NBUF   6               // rotating future total buffers
#define CSLOT  80              // fixed CSR slots per source neuron (mean fanout 30)

#define U_BLKS   196           // ceil(50000/256)
#define I_BLKS   196           // input-scatter role blocks
#define F_GRID   (U_BLKS + I_BLKS)

// ------------------------- device scratch (no allocs) -------------------------
__device__ float4         g_tot[NBUF][BB * NN];   // 6 x 6.4 MB
__device__ float          g_v[BB * NN];
__device__ float          g_r[BB * NN];
__device__ float          g_a1[BB * NN];
__device__ float          g_a2[BB * NN];
__device__ float4         g_psc_rise[BB * NN];
__device__ float4         g_psc[BB * NN];
__device__ unsigned char  g_prevz[NN];            // spike mask of previous step
__device__ unsigned char  g_xmask[TT * N_INN];    // packed input spikes
__device__ float2         g_ascd[NN];

// full outgoing CSR: fixed-slot buckets per source neuron, meta = (d<<18)|tgt
__device__ int            g_fillC[NN];            // cursor, init = n*CSLOT
__device__ int2           g_cedge[NN * CSLOT];    // (meta, w-bits)

// ------------------------------- init kernel ---------------------------------
__global__ void init_kernel(const float* __restrict__ x,
                            const float* __restrict__ bkg_w,
                            const float2* __restrict__ param_k,
                            const float* __restrict__ v0)
{
    int i      = blockIdx.x * blockDim.x + threadIdx.x;
    int stride = gridDim.x * blockDim.x;

    const float4* bkg4 = reinterpret_cast<const float4*>(bkg_w);
    for (int j = i; j < BB * NN; j += stride) {
        float4 bk = bkg4[j % NN];
        #pragma unroll
        for (int s = 0; s < NBUF; s++) g_tot[s][j] = bk;
        g_v[j]  = v0[j];
        g_r[j]  = 0.0f;
        g_a1[j] = 0.0f;
        g_a2[j] = 0.0f;
        g_psc_rise[j] = make_float4(0.f, 0.f, 0.f, 0.f);
        g_psc[j]      = make_float4(0.f, 0.f, 0.f, 0.f);
    }
    for (int j = i; j < NN; j += stride) {
        g_prevz[j] = 0;
        g_fillC[j] = j * CSLOT;
    }
    for (int j = i; j < TT * N_INN; j += stride) {
        int t = j / N_INN;
        int s = j - t * N_INN;
        unsigned m = 0;
        #pragma unroll
        for (int b = 0; b < BB; b++) {
            if (x[(t * BB + b) * N_INN + s] > 0.5f) m |= (1u << b);
        }
        g_xmask[j] = (unsigned char)m;
    }
    for (int j = i; j < NN; j += stride) {
        float2 pk = param_k[j];
        float s0 = 1.0f / (1.0f + expf(-pk.x));
        float s1 = 1.0f / (1.0f + expf(-pk.y));
        g_ascd[j] = make_float2(expf(-s0), expf(-s1));
    }
}

// ---------------------- build per-source CSR (fixed slots) ---------------------
__global__ __launch_bounds__(256)
void partition_kernel(const int* __restrict__ rec_src,
                      const int* __restrict__ rec_tgt,
                      const float* __restrict__ w_rec)
{
    int i      = blockIdx.x * blockDim.x + threadIdx.x;
    int stride = gridDim.x * blockDim.x;
    for (int e = i; e < E_RECN; e += stride) {
        int src = rec_src[e];
        int d = src / NN;
        int n = src - d * NN;
        int meta = (d << 18) | rec_tgt[e];
        int pos = atomicAdd(&g_fillC[n], 1);
        g_cedge[pos] = make_int2(meta, __float_as_int(w_rec[e]));
    }
}

// ---------------------- step-0 input scatter ------------------------------------
__global__ __launch_bounds__(256)
void s0_kernel(const int* __restrict__ in_src,
               const int* __restrict__ in_tgt,
               const float* __restrict__ w_in)
{
    int q = blockIdx.x * blockDim.x + threadIdx.x;
    if (q >= IN_QUADS) return;
    float* tot = reinterpret_cast<float*>(g_tot[0]);
    const int e0 = q * 4;
    int4 si = *reinterpret_cast<const int4*>(&in_src[e0]);
    const unsigned char* xm = &g_xmask[0];
    unsigned m0 = xm[si.x], m1 = xm[si.y], m2 = xm[si.z], m3 = xm[si.w];
    if ((m0 | m1 | m2 | m3) == 0u) return;
    int4   tg = *reinterpret_cast<const int4*>  (&in_tgt[e0]);
    float4 ww = *reinterpret_cast<const float4*>(&w_in[e0]);
    unsigned ms[4]  = {m0, m1, m2, m3};
    int      tgs[4] = {tg.x, tg.y, tg.z, tg.w};
    float    wws[4] = {ww.x, ww.y, ww.z, ww.w};
    #pragma unroll
    for (int k = 0; k < 4; k++) {
        unsigned m = ms[k];
        if (!m) continue;
        #pragma unroll
        for (int b = 0; b < BB; b++) {
            if (m & (1u << b)) atomicAdd(&tot[b * RNN + tgs[k]], wws[k]);
        }
    }
}

// ------------------------------ fused step kernel -------------------------------
// Blocks [0, U_BLKS): update step t; spiking neurons walk their CSR row and
//   scatter into future buffers tot[(t+1+d) % NBUF].
// Blocks [U_BLKS, F_GRID): input scatter for step t+1 into tot[(t+1) % NBUF].
__global__ __launch_bounds__(256)
void fused_kernel(const float*  __restrict__ decay,
                  const float*  __restrict__ current_factor,
                  const float*  __restrict__ v_th,
                  const float*  __restrict__ e_l,
                  const float*  __restrict__ v_reset,
                  const float*  __restrict__ t_ref,
                  const float2* __restrict__ asc_amps,
                  const float*  __restrict__ param_g,
                  const float4* __restrict__ syn_decay,
                  const float4* __restrict__ psc_initial,
                  const float4* __restrict__ bkg4,
                  const int*    __restrict__ in_src,
                  const int*    __restrict__ in_tgt,
                  const float*  __restrict__ w_in,
                  float*        __restrict__ out,
                  int t)
{
    if (blockIdx.x < U_BLKS) {
        // ------------------------- update role -------------------------------
        int n = blockIdx.x * blockDim.x + threadIdx.x;
        if (n >= NN) return;

        float4* totcur = g_tot[t % NBUF];

        const float  dec  = decay[n];
        const float  cf   = current_factor[n];
        const float  vth  = v_th[n];
        const float  el   = e_l[n];
        const float  vre  = v_reset[n];
        const float  tref = t_ref[n];
        const float2 amps = asc_amps[n];
        const float2 ad   = g_ascd[n];
        const float  g    = param_g[n];
        const float4 sd   = syn_decay[n];
        const float4 pi   = psc_initial[n];
        const float4 bk   = bkg4[n];

        const float gel    = g * el;
        const float invden = 1.0f / (vth - el);
        const float rstamp = vre - vth;

        unsigned pm = g_prevz[n];
        unsigned nm = 0;

        #pragma unroll
        for (int b = 0; b < BB; b++) {
            int bn = b * NN + n;
            float4 total = totcur[bn];
            float4 pr = g_psc_rise[bn];
            float4 pc = g_psc[bn];
            float  v  = g_v[bn];
            float  r  = g_r[bn];
            float  a1 = g_a1[bn];
            float  a2 = g_a2[bn];
            float  pz = (pm >> b) & 1u ? 1.0f : 0.0f;

            float input_cur = pc.x + pc.y + pc.z + pc.w;
            float c1   = input_cur + a1 + a2 + gel;
            float newv = dec * v + cf * c1 + pz * rstamp;
            float newr = fmaxf(r + pz * tref - 1.0f, 0.0f);
            float na1  = ad.x * a1 + pz * amps.x;
            float na2  = ad.y * a2 + pz * amps.y;

            float4 npc, npr;
            npc.x = pc.x * sd.x + sd.x * pr.x;
            npc.y = pc.y * sd.y + sd.y * pr.y;
            npc.z = pc.z * sd.z + sd.z * pr.z;
            npc.w = pc.w * sd.w + sd.w * pr.w;
            npr.x = sd.x * pr.x + pi.x * total.x;
            npr.y = sd.y * pr.y + pi.y * total.y;
            npr.z = sd.z * pr.z + pi.z * total.z;
            npr.w = sd.w * pr.w + pi.w * total.w;

            float vsc = (newv - vth) * invden;
            float z = (vsc > 0.0f) ? 1.0f : 0.0f;
            if (newr > 0.0f) z = 0.0f;
            nm |= (z != 0.0f ? 1u : 0u) << b;

            g_v[bn]  = newv;
            g_r[bn]  = newr;
            g_a1[bn] = na1;
            g_a2[bn] = na2;
            g_psc_rise[bn] = npr;
            g_psc[bn]      = npc;
            totcur[bn] = bk;                 // re-init for step t+NBUF

            __stcs(&out[(t * BB + b) * NN + n], z);
        }
        g_prevz[n] = (unsigned char)nm;

        // event-driven scatter: walk my outgoing CSR row once
        if (nm) {
            int r0 = n * CSLOT;
            int r1 = g_fillC[n];
            for (int e = r0; e < r1; e++) {
                int2 tw = g_cedge[e];
                int  d   = tw.x >> 18;
                int  tgt = tw.x & 0x3FFFF;
                int  ts  = t + 1 + d;
                if (ts >= TT) continue;
                float w = __int_as_float(tw.y);
                float* totf = reinterpret_cast<float*>(g_tot[ts % NBUF]);
                #pragma unroll
                for (int b = 0; b < BB; b++) {
                    if (nm & (1u << b)) atomicAdd(&totf[b * RNN + tgt], w);
                }
            }
        }
    } else {
        // --------------------- input scatter role (step t+1) ------------------
        if (t + 1 >= TT) return;
        const int tau = t + 1;
        float* totn = reinterpret_cast<float*>(g_tot[tau % NBUF]);

        int idx    = (blockIdx.x - U_BLKS) * blockDim.x + threadIdx.x;
        int stride = (gridDim.x - U_BLKS) * blockDim.x;

        for (int q = idx; q < IN_QUADS; q += stride) {
            const int e0 = q * 4;
            int4 si = *reinterpret_cast<const int4*>(&in_src[e0]);
            const unsigned char* xm = &g_xmask[tau * N_INN];
            unsigned m0 = xm[si.x], m1 = xm[si.y], m2 = xm[si.z], m3 = xm[si.w];
            if ((m0 | m1 | m2 | m3) == 0u) continue;

            int4   tg = *reinterpret_cast<const int4*>  (&in_tgt[e0]);
            float4 ww = *reinterpret_cast<const float4*>(&w_in[e0]);
            unsigned ms[4]  = {m0, m1, m2, m3};
            int      tgs[4] = {tg.x, tg.y, tg.z, tg.w};
            float    wws[4] = {ww.x, ww.y, ww.z, ww.w};
            #pragma unroll
            for (int k = 0; k < 4; k++) {
                unsigned m = ms[k];
                if (!m) continue;
                #pragma unroll
                for (int b = 0; b < BB; b++) {
                    if (m & (1u << b)) atomicAdd(&totn[b * RNN + tgs[k]], wws[k]);
                }
            }
        }
    }
}

// --------------------------------- launcher ----------------------------------
extern "C" void kernel_launch(void* const* d_in, const int* in_sizes, int n_in,
                              void* d_out, int out_size)
{
    const float* x        = (const float*)d_in[0];
    const float* w_rec    = (const float*)d_in[1];
    const int*   rec_src  = (const int*)  d_in[2];
    const int*   rec_tgt  = (const int*)  d_in[3];
    const float* w_in     = (const float*)d_in[4];
    const int*   in_src   = (const int*)  d_in[5];
    const int*   in_tgt   = (const int*)  d_in[6];
    const float* bkg_w    = (const float*)d_in[7];
    const float* decay    = (const float*)d_in[8];
    const float* cf       = (const float*)d_in[9];
    const float* v_th     = (const float*)d_in[10];
    const float* e_l      = (const float*)d_in[11];
    const float* v_reset  = (const float*)d_in[12];
    const float* t_ref    = (const float*)d_in[13];
    const float2* asc_amps = (const float2*)d_in[14];
    const float2* param_k  = (const float2*)d_in[15];
    const float* param_g   = (const float*)d_in[16];
    const float4* syn_decay   = (const float4*)d_in[17];
    const float4* psc_initial = (const float4*)d_in[18];
    const float* v0        = (const float*)d_in[19];
    float* out = (float*)d_out;

    init_kernel<<<1024, 256>>>(x, bkg_w, param_k, v0);
    partition_kernel<<<(E_RECN + 255) / 256, 256>>>(rec_src, rec_tgt, w_rec);
    s0_kernel<<<(IN_QUADS + 255) / 256, 256>>>(in_src, in_tgt, w_in);

    for (int t = 0; t < TT; t++) {
        fused_kernel<<<F_GRID, 256>>>(decay, cf, v_th, e_l, v_reset, t_ref,
                                      asc_amps, param_g, syn_decay, psc_initial,
                                      (const float4*)bkg_w,
                                      in_src, in_tgt, w_in,
                                      out, t);
    }
}

// round 11
// speedup vs baseline: 1.1194x; 1.1194x over previous
#include <cuda_runtime.h>
#include <math.h>

#define NN     50000
#define RR     4
#define DD     5
#define BB     8
#define TT     10
#define E_RECN 1500000
#define E_INN  200000
#define N_INN  17400
#define RNN    (RR * NN)   // 200000
#define ZLEN   (DD * NN)   // 250000
#define IN_QUADS (E_INN / 4)   // 50000

#define BKT    32               // fixed slots per (delay, source) bucket, mean 6
#define NBKT   (DD * NN)        // 250000 buckets (d = 0..4)

#define U_BLKS   196            // ceil(50000/256) update-role blocks
#define SE_BLKS  1080           // scatter-role blocks (>= (4*NN+IN_QUADS)/256)
#define F_GRID   (U_BLKS + SE_BLKS)

// ------------------------- device scratch (no allocs) -------------------------
__device__ float4         g_totA[BB * NN];
__device__ float4         g_totB[BB * NN];
__device__ float          g_v[BB * NN];
__device__ float          g_r[BB * NN];
__device__ float          g_a1[BB * NN];
__device__ float          g_a2[BB * NN];
__device__ float4         g_psc_rise[BB * NN];
__device__ float4         g_psc[BB * NN];
__device__ unsigned char  g_zmask[ZLEN];
__device__ unsigned char  g_xmask[TT * N_INN];
__device__ float2         g_ascd[NN];

// (delay, source)-bucketed edges: bucket bi = d*NN + n, fixed BKT slots
__device__ int            g_bfill[NBKT];          // cursor, init = bi*BKT
__device__ unsigned char  g_bcnt[NBKT];           // final count (<= BKT)
__device__ int2           g_bedge[NBKT * BKT];    // (tgt, w-bits)  64 MB

// per-source-step spike activity flags: g_any[5 + s] for step s (s in [-5, TT))
__device__ int            g_any[16];

// ------------------------------- init kernel ---------------------------------
__global__ void init_kernel(const float* __restrict__ x,
                            const float* __restrict__ bkg_w,
                            const float2* __restrict__ param_k,
                            const float* __restrict__ v0)
{
    int i      = blockIdx.x * blockDim.x + threadIdx.x;
    int stride = gridDim.x * blockDim.x;

    if (i < 16) g_any[i] = 0;

    const float4* bkg4 = reinterpret_cast<const float4*>(bkg_w);
    for (int j = i; j < BB * NN; j += stride) {
        float4 bk = bkg4[j % NN];
        g_totA[j] = bk;
        g_totB[j] = bk;
        g_v[j]  = v0[j];
        g_r[j]  = 0.0f;
        g_a1[j] = 0.0f;
        g_a2[j] = 0.0f;
        g_psc_rise[j] = make_float4(0.f, 0.f, 0.f, 0.f);
        g_psc[j]      = make_float4(0.f, 0.f, 0.f, 0.f);
    }
    for (int j = i; j < ZLEN; j += stride) g_zmask[j] = 0;
    for (int j = i; j < NBKT; j += stride) g_bfill[j] = j * BKT;
    for (int j = i; j < TT * N_INN; j += stride) {
        int t = j / N_INN;
        int s = j - t * N_INN;
        unsigned m = 0;
        #pragma unroll
        for (int b = 0; b < BB; b++) {
            if (x[(t * BB + b) * N_INN + s] > 0.5f) m |= (1u << b);
        }
        g_xmask[j] = (unsigned char)m;
    }
    for (int j = i; j < NN; j += stride) {
        float2 pk = param_k[j];
        float s0 = 1.0f / (1.0f + expf(-pk.x));
        float s1 = 1.0f / (1.0f + expf(-pk.y));
        g_ascd[j] = make_float2(expf(-s0), expf(-s1));
    }
}

// ---------------------- partition edges into buckets ---------------------------
__global__ __launch_bounds__(256)
void partition_kernel(const int* __restrict__ rec_src,
                      const int* __restrict__ rec_tgt,
                      const float* __restrict__ w_rec)
{
    int i      = blockIdx.x * blockDim.x + threadIdx.x;
    int stride = gridDim.x * blockDim.x;
    for (int e = i; e < E_RECN; e += stride) {
        int bi = rec_src[e];                    // src = d*NN + n == bucket index
        int pos = atomicAdd(&g_bfill[bi], 1);
        g_bedge[pos] = make_int2(rec_tgt[e], __float_as_int(w_rec[e]));
    }
}

// -------- step-0 input scatter + bucket-count finalize --------------------------
__global__ __launch_bounds__(256)
void s0_kernel(const int* __restrict__ in_src,
               const int* __restrict__ in_tgt,
               const float* __restrict__ w_in)
{
    int i      = blockIdx.x * blockDim.x + threadIdx.x;
    int stride = gridDim.x * blockDim.x;

    // finalize bucket counts (fill - base), fits in uchar
    for (int j = i; j < NBKT; j += stride)
        g_bcnt[j] = (unsigned char)(g_bfill[j] - j * BKT);

    int q = i;
    if (q >= IN_QUADS) return;
    float* tot = reinterpret_cast<float*>(g_totA);
    const int e0 = q * 4;
    int4 si = *reinterpret_cast<const int4*>(&in_src[e0]);
    const unsigned char* xm = &g_xmask[0];
    unsigned m0 = xm[si.x], m1 = xm[si.y], m2 = xm[si.z], m3 = xm[si.w];
    if ((m0 | m1 | m2 | m3) == 0u) return;
    int4   tg = *reinterpret_cast<const int4*>  (&in_tgt[e0]);
    float4 ww = *reinterpret_cast<const float4*>(&w_in[e0]);
    unsigned ms[4]  = {m0, m1, m2, m3};
    int      tgs[4] = {tg.x, tg.y, tg.z, tg.w};
    float    wws[4] = {ww.x, ww.y, ww.z, ww.w};
    #pragma unroll
    for (int k = 0; k < 4; k++) {
        unsigned m = ms[k];
        if (!m) continue;
        #pragma unroll
        for (int b = 0; b < BB; b++) {
            if (m & (1u << b)) atomicAdd(&tot[b * RNN + tgs[k]], wws[k]);
        }
    }
}

// ------------------------------ fused step kernel -------------------------------
// Blocks [0, U_BLKS): update step t; also walks own d=0 bucket into tot(t+1).
// Blocks [U_BLKS, F_GRID): scatter for step t+1: one thread per (d,n) pair,
//   coalesced zmask/count reads, edge data touched only for spiking sources;
//   plus input-edge quads for step t+1.
__global__ __launch_bounds__(256)
void fused_kernel(const float*  __restrict__ decay,
                  const float*  __restrict__ current_factor,
                  const float*  __restrict__ v_th,
                  const float*  __restrict__ e_l,
                  const float*  __restrict__ v_reset,
                  const float*  __restrict__ t_ref,
                  const float2* __restrict__ asc_amps,
                  const float*  __restrict__ param_g,
                  const float4* __restrict__ syn_decay,
                  const float4* __restrict__ psc_initial,
                  const float4* __restrict__ bkg4,
                  const int*    __restrict__ in_src,
                  const int*    __restrict__ in_tgt,
                  const float*  __restrict__ w_in,
                  float*        __restrict__ out,
                  int t, int h_read, int h_write)
{
    float4* totcur = (t & 1) ? g_totB : g_totA;
    float4* totnxt = (t & 1) ? g_totA : g_totB;

    if (blockIdx.x < U_BLKS) {
        // ------------------------- update role -------------------------------
        int n = blockIdx.x * blockDim.x + threadIdx.x;
        if (n >= NN) return;

        const float  dec  = decay[n];
        const float  cf   = current_factor[n];
        const float  vth  = v_th[n];
        const float  el   = e_l[n];
        const float  vre  = v_reset[n];
        const float  tref = t_ref[n];
        const float2 amps = asc_amps[n];
        const float2 ad   = g_ascd[n];
        const float  g    = param_g[n];
        const float4 sd   = syn_decay[n];
        const float4 pi   = psc_initial[n];
        const float4 bk   = bkg4[n];

        const float gel    = g * el;
        const float invden = 1.0f / (vth - el);
        const float rstamp = vre - vth;

        unsigned pm = g_zmask[h_read * NN + n];
        unsigned nm = 0;

        #pragma unroll
        for (int b = 0; b < BB; b++) {
            int bn = b * NN + n;
            float4 total = totcur[bn];
            float4 pr = g_psc_rise[bn];
            float4 pc = g_psc[bn];
            float  v  = g_v[bn];
            float  r  = g_r[bn];
            float  a1 = g_a1[bn];
            float  a2 = g_a2[bn];
            float  pz = (pm >> b) & 1u ? 1.0f : 0.0f;

            float input_cur = pc.x + pc.y + pc.z + pc.w;
            float c1   = input_cur + a1 + a2 + gel;
            float newv = dec * v + cf * c1 + pz * rstamp;
            float newr = fmaxf(r + pz * tref - 1.0f, 0.0f);
            float na1  = ad.x * a1 + pz * amps.x;
            float na2  = ad.y * a2 + pz * amps.y;

            float4 npc, npr;
            npc.x = pc.x * sd.x + sd.x * pr.x;
            npc.y = pc.y * sd.y + sd.y * pr.y;
            npc.z = pc.z * sd.z + sd.z * pr.z;
            npc.w = pc.w * sd.w + sd.w * pr.w;
            npr.x = sd.x * pr.x + pi.x * total.x;
            npr.y = sd.y * pr.y + pi.y * total.y;
            npr.z = sd.z * pr.z + pi.z * total.z;
            npr.w = sd.w * pr.w + pi.w * total.w;

            float vsc = (newv - vth) * invden;
            float z = (vsc > 0.0f) ? 1.0f : 0.0f;
            if (newr > 0.0f) z = 0.0f;
            nm |= (z != 0.0f ? 1u : 0u) << b;

            g_v[bn]  = newv;
            g_r[bn]  = newr;
            g_a1[bn] = na1;
            g_a2[bn] = na2;
            g_psc_rise[bn] = npr;
            g_psc[bn]      = npc;
            totcur[bn] = bk;                 // re-init for step t+2

            __stcs(&out[(t * BB + b) * NN + n], z);
        }
        g_zmask[h_write * NN + n] = (unsigned char)nm;

        if (nm) {
            g_any[5 + t] = 1;                // benign race (all write 1)
            if (t + 1 < TT) {
                // d=0 bucket (bi = n): scatter own fan-out into next totals
                float* totn = reinterpret_cast<float*>(totnxt);
                int base = n * BKT;
                int cnt  = g_bcnt[n];
                for (int e = base; e < base + cnt; e++) {
                    int2 tw = g_bedge[e];
                    float w = __int_as_float(tw.y);
                    #pragma unroll
                    for (int b = 0; b < BB; b++) {
                        if (nm & (1u << b)) atomicAdd(&totn[b * RNN + tw.x], w);
                    }
                }
            }
        }
    } else {
        // --------------------- scatter role (step t+1) -----------------------
        if (t + 1 >= TT) return;
        const int tau = t + 1;
        float* totn = reinterpret_cast<float*>(totnxt);

        const int NIT = 4 * NN;                 // (d,n) pairs for d=1..4
        const int totw = NIT + IN_QUADS;

        int idx    = (blockIdx.x - U_BLKS) * blockDim.x + threadIdx.x;
        int stride = (gridDim.x - U_BLKS) * blockDim.x;

        for (int it = idx; it < totw; it += stride) {
            if (it < NIT) {
                int d = 1 + (it >= NN) + (it >= 2 * NN) + (it >= 3 * NN);
                if (g_any[5 + t - d] == 0) continue;   // source step had no spikes
                int n = it - (d - 1) * NN;

                int slot = h_write + d; if (slot >= DD) slot -= DD;
                unsigned m = g_zmask[slot * NN + n];   // coalesced (consecutive n)
                if (!m) continue;

                int bi   = d * NN + n;
                int cnt  = g_bcnt[bi];                 // coalesced byte
                int base = bi * BKT;
                for (int e = base; e < base + cnt; e++) {
                    int2 tw = g_bedge[e];
                    float w = __int_as_float(tw.y);
                    #pragma unroll
                    for (int b = 0; b < BB; b++) {
                        if (m & (1u << b)) atomicAdd(&totn[b * RNN + tw.x], w);
                    }
                }
            } else {
                const int e0 = (it - NIT) * 4;
                int4 si = *reinterpret_cast<const int4*>(&in_src[e0]);
                const unsigned char* xm = &g_xmask[tau * N_INN];
                unsigned m0 = xm[si.x], m1 = xm[si.y], m2 = xm[si.z], m3 = xm[si.w];
                if ((m0 | m1 | m2 | m3) == 0u) continue;

                int4   tg = *reinterpret_cast<const int4*>  (&in_tgt[e0]);
                float4 ww = *reinterpret_cast<const float4*>(&w_in[e0]);
                unsigned ms[4]  = {m0, m1, m2, m3};
                int      tgs[4] = {tg.x, tg.y, tg.z, tg.w};
                float    wws[4] = {ww.x, ww.y, ww.z, ww.w};
                #pragma unroll
                for (int k = 0; k < 4; k++) {
                    unsigned m = ms[k];
                    if (!m) continue;
                    #pragma unroll
                    for (int b = 0; b < BB; b++) {
                        if (m & (1u << b)) atomicAdd(&totn[b * RNN + tgs[k]], wws[k]);
                    }
                }
            }
        }
    }
}

// --------------------------------- launcher ----------------------------------
extern "C" void kernel_launch(void* const* d_in, const int* in_sizes, int n_in,
                              void* d_out, int out_size)
{
    const float* x        = (const float*)d_in[0];
    const float* w_rec    = (const float*)d_in[1];
    const int*   rec_src  = (const int*)  d_in[2];
    const int*   rec_tgt  = (const int*)  d_in[3];
    const float* w_in     = (const float*)d_in[4];
    const int*   in_src   = (const int*)  d_in[5];
    const int*   in_tgt   = (const int*)  d_in[6];
    const float* bkg_w    = (const float*)d_in[7];
    const float* decay    = (const float*)d_in[8];
    const float* cf       = (const float*)d_in[9];
    const float* v_th     = (const float*)d_in[10];
    const float* e_l      = (const float*)d_in[11];
    const float* v_reset  = (const float*)d_in[12];
    const float* t_ref    = (const float*)d_in[13];
    const float2* asc_amps = (const float2*)d_in[14];
    const float2* param_k  = (const float2*)d_in[15];
    const float* param_g   = (const float*)d_in[16];
    const float4* syn_decay   = (const float4*)d_in[17];
    const float4* psc_initial = (const float4*)d_in[18];
    const float* v0        = (const float*)d_in[19];
    float* out = (float*)d_out;

    init_kernel<<<1024, 256>>>(x, bkg_w, param_k, v0);
    partition_kernel<<<(E_RECN + 255) / 256, 256>>>(rec_src, rec_tgt, w_rec);
    s0_kernel<<<(IN_QUADS + 255) / 256, 256>>>(in_src, in_tgt, w_in);

    int h = 0;
    for (int t = 0; t < TT; t++) {
        int h_read  = h;
        int h_write = (h + DD - 1) % DD;
        fused_kernel<<<F_GRID, 256>>>(decay, cf, v_th, e_l, v_reset, t_ref,
                                      asc_amps, param_g, syn_decay, psc_initial,
                                      (const float4*)bkg_w,
                                      in_src, in_tgt, w_in,
                                      out, t, h_read, h_write);
        h = h_write;
    }
}